// round 5
// baseline (speedup 1.0000x reference)
#include <cuda_runtime.h>
#include <math.h>

// Problem constants (fixed by the reference)
#define C_     512
#define G_     4
#define CG_    128
#define R_     16
#define TOPK_  384
#define HW_    12544          // 112*112
#define T1     448            // threads for pool/blend kernels
#define PER_T  7              // float4s per thread: 448*7 = 3136 = HW_/4
#define TAU_INV 2.0f          // 1/0.5
#define ALPHA_ 0.1f
#define EPS_   1e-8f

// Scratch: [B=16, C=512] each. No allocations allowed -> __device__ globals.
__device__ float g_avg[16 * C_];
__device__ float g_mx [16 * C_];
__device__ float g_blend[16 * C_];

// ---------------------------------------------------------------------------
// Kernel 1: per-(b,c) avg + max pooling over HW. One block per (b,c).
// ---------------------------------------------------------------------------
__global__ __launch_bounds__(T1) void pool_kernel(const float* __restrict__ x)
{
    const int bc = blockIdx.x;
    const float4* __restrict__ xp =
        reinterpret_cast<const float4*>(x + (size_t)bc * HW_);
    const int t = threadIdx.x;

    // Two independent accumulator chains for ILP.
    float s0 = 0.0f, s1 = 0.0f;
    float m0 = -INFINITY, m1 = -INFINITY;
#pragma unroll
    for (int k = 0; k < PER_T; k++) {
        float4 v = xp[t + k * T1];
        if (k & 1) {
            s1 += (v.x + v.y) + (v.z + v.w);
            m1 = fmaxf(m1, fmaxf(fmaxf(v.x, v.y), fmaxf(v.z, v.w)));
        } else {
            s0 += (v.x + v.y) + (v.z + v.w);
            m0 = fmaxf(m0, fmaxf(fmaxf(v.x, v.y), fmaxf(v.z, v.w)));
        }
    }
    float s = s0 + s1;
    float m = fmaxf(m0, m1);

    // warp reduction
#pragma unroll
    for (int o = 16; o > 0; o >>= 1) {
        s += __shfl_down_sync(0xffffffffu, s, o);
        m = fmaxf(m, __shfl_down_sync(0xffffffffu, m, o));
    }

    __shared__ float ss[T1 / 32];
    __shared__ float sm[T1 / 32];
    const int w = t >> 5, lane = t & 31;
    if (lane == 0) { ss[w] = s; sm[w] = m; }
    __syncthreads();

    if (t == 0) {
        float S = ss[0], M = sm[0];
#pragma unroll
        for (int i = 1; i < T1 / 32; i++) {
            S += ss[i];
            M = fmaxf(M, sm[i]);
        }
        g_avg[bc] = S * (1.0f / (float)HW_);
        g_mx [bc] = M;
    }
}

// ---------------------------------------------------------------------------
// Kernel 2: per-batch grouped MLP -> score -> exact top-k mask -> gumbel
// sigmoid -> blend factor. One 512-thread block per batch; thread t = channel.
// ---------------------------------------------------------------------------
__global__ __launch_bounds__(C_) void score_kernel(
    const float* __restrict__ W1, const float* __restrict__ b1,
    const float* __restrict__ W2, const float* __restrict__ b2,
    const float* __restrict__ noise_u)
{
    const int b = blockIdx.x;
    const int t = threadIdx.x;

    __shared__ float comb[2 * C_];   // [avg(512), max(512)] = concat order
    __shared__ float hsm[G_ * R_];   // 64 hidden relu values
    __shared__ float scores[C_];

    comb[t]       = g_avg[b * C_ + t];
    comb[C_ + t]  = g_mx [b * C_ + t];
    __syncthreads();

    // Hidden layer: 64 (g,r) pairs, each a 256-dot against comb[g*256 .. ].
    // Group g consumes combined[g*2CG : (g+1)*2CG] (mixed avg/max slices).
    if (t < G_ * R_) {
        const int g = t >> 4, r = t & 15;
        float acc = b1[g * R_ + r];
        const float* __restrict__ w1p = W1 + (size_t)g * (2 * CG_) * R_ + r;
        const float* gf = comb + g * (2 * CG_);
#pragma unroll 8
        for (int i = 0; i < 2 * CG_; i++)
            acc = fmaf(gf[i], w1p[(size_t)i * R_], acc);
        hsm[t] = fmaxf(acc, 0.0f);
    }
    __syncthreads();

    // Output layer: score[c], c = t; group g = t/128, o = t%128.
    const int g = t >> 7, o = t & 127;
    float sc = b2[g * CG_ + o];
    const float* __restrict__ w2p = W2 + (size_t)g * R_ * CG_ + o;
#pragma unroll
    for (int r = 0; r < R_; r++)
        sc = fmaf(hsm[g * R_ + r], w2p[(size_t)r * CG_], sc);
    scores[t] = sc;
    __syncthreads();

    // Exact top-k rank: matches jax.lax.top_k (descending value, lowest index
    // wins ties). Broadcast smem reads: all threads read scores[j] together.
    int rank = 0;
    for (int j = 0; j < C_; j++) {
        const float sj = scores[j];
        rank += (sj > sc) || (sj == sc && j < t);
    }
    const float hard = (rank < TOPK_) ? 1.0f : 0.0f;

    // Gumbel-sigmoid soft score (precise logf/expf: 8192 threads total, cheap)
    const float u   = noise_u[b * C_ + t];
    const float gum = -logf(-logf(u + EPS_) + EPS_);
    const float z   = (sc + gum) * TAU_INV;
    const float soft = 1.0f / (1.0f + expf(-z));

    const float mask = hard * soft;
    g_blend[b * C_ + t] = mask + (1.0f - mask) * ALPHA_;
}

// ---------------------------------------------------------------------------
// Kernel 3: out = x * blend[b,c]. One block per (b,c), float4 vectorized.
// x is never read again and out is never re-read -> streaming cache hints.
// ---------------------------------------------------------------------------
__global__ __launch_bounds__(T1) void blend_kernel(
    const float* __restrict__ x, float* __restrict__ out)
{
    const int bc = blockIdx.x;
    const float bl = g_blend[bc];
    const size_t base = (size_t)bc * HW_;
    const float4* __restrict__ xp = reinterpret_cast<const float4*>(x + base);
    float4* __restrict__ op       = reinterpret_cast<float4*>(out + base);
    const int t = threadIdx.x;
#pragma unroll
    for (int k = 0; k < PER_T; k++) {
        const int i = t + k * T1;
        float4 v = __ldcs(&xp[i]);      // evict-first load
        v.x *= bl; v.y *= bl; v.z *= bl; v.w *= bl;
        __stcs(&op[i], v);              // streaming store
    }
}

// ---------------------------------------------------------------------------
extern "C" void kernel_launch(void* const* d_in, const int* in_sizes, int n_in,
                              void* d_out, int out_size)
{
    const float* x  = (const float*)d_in[0];
    const float* W1 = (const float*)d_in[1];
    const float* b1 = (const float*)d_in[2];
    const float* W2 = (const float*)d_in[3];
    const float* b2 = (const float*)d_in[4];
    const float* nu = (const float*)d_in[5];
    float* out = (float*)d_out;

    const int B  = in_sizes[5] / C_;   // noise_u is [B, C]
    const int BC = B * C_;

    pool_kernel <<<BC, T1>>>(x);
    score_kernel<<<B,  C_>>>(W1, b1, W2, b2, nu);
    blend_kernel<<<BC, T1>>>(x, out);
}

// round 7
// speedup vs baseline: 1.0188x; 1.0188x over previous
#include <cuda_runtime.h>
#include <math.h>

// Problem constants (fixed by the reference)
#define C_     512
#define G_     4
#define CG_    128
#define R_     16
#define TOPK_  384
#define HW_    12544          // 112*112
#define T1     448            // threads for pool/blend kernels
#define PER_T  7              // float4s per thread: 448*7 = 3136 = HW_/4
#define TAU_INV 2.0f          // 1/0.5
#define ALPHA_ 0.1f
#define EPS_   1e-8f

// Scratch: [B=16, C=512] each. No allocations allowed -> __device__ globals.
__device__ float g_avg[16 * C_];
__device__ float g_mx [16 * C_];
__device__ float g_blend[16 * C_];

// ---------------------------------------------------------------------------
// Kernel 1: per-(b,c) avg + max pooling over HW. One block per (b,c).
// Measured R5: 62.5us, 83.8% DRAM, 6638 GB/s -> at the roofline. Unchanged.
// ---------------------------------------------------------------------------
__global__ __launch_bounds__(T1) void pool_kernel(const float* __restrict__ x)
{
    const int bc = blockIdx.x;
    const float4* __restrict__ xp =
        reinterpret_cast<const float4*>(x + (size_t)bc * HW_);
    const int t = threadIdx.x;

    // Two independent accumulator chains for ILP.
    float s0 = 0.0f, s1 = 0.0f;
    float m0 = -INFINITY, m1 = -INFINITY;
#pragma unroll
    for (int k = 0; k < PER_T; k++) {
        float4 v = xp[t + k * T1];
        if (k & 1) {
            s1 += (v.x + v.y) + (v.z + v.w);
            m1 = fmaxf(m1, fmaxf(fmaxf(v.x, v.y), fmaxf(v.z, v.w)));
        } else {
            s0 += (v.x + v.y) + (v.z + v.w);
            m0 = fmaxf(m0, fmaxf(fmaxf(v.x, v.y), fmaxf(v.z, v.w)));
        }
    }
    float s = s0 + s1;
    float m = fmaxf(m0, m1);

    // warp reduction
#pragma unroll
    for (int o = 16; o > 0; o >>= 1) {
        s += __shfl_down_sync(0xffffffffu, s, o);
        m = fmaxf(m, __shfl_down_sync(0xffffffffu, m, o));
    }

    __shared__ float ss[T1 / 32];
    __shared__ float sm[T1 / 32];
    const int w = t >> 5, lane = t & 31;
    if (lane == 0) { ss[w] = s; sm[w] = m; }
    __syncthreads();

    if (t == 0) {
        float S = ss[0], M = sm[0];
#pragma unroll
        for (int i = 1; i < T1 / 32; i++) {
            S += ss[i];
            M = fmaxf(M, sm[i]);
        }
        g_avg[bc] = S * (1.0f / (float)HW_);
        g_mx [bc] = M;
    }
}

// ---------------------------------------------------------------------------
// Kernel 2: per-batch grouped MLP -> score -> exact top-k mask -> gumbel
// sigmoid -> blend factor. One 512-thread block per batch; thread t = channel.
// ---------------------------------------------------------------------------
__global__ __launch_bounds__(C_) void score_kernel(
    const float* __restrict__ W1, const float* __restrict__ b1,
    const float* __restrict__ W2, const float* __restrict__ b2,
    const float* __restrict__ noise_u)
{
    const int b = blockIdx.x;
    const int t = threadIdx.x;

    __shared__ float comb[2 * C_];   // [avg(512), max(512)] = concat order
    __shared__ float hsm[G_ * R_];   // 64 hidden relu values
    __shared__ float scores[C_];

    comb[t]       = g_avg[b * C_ + t];
    comb[C_ + t]  = g_mx [b * C_ + t];
    __syncthreads();

    // Hidden layer: 64 (g,r) pairs, each a 256-dot against comb[g*256 .. ].
    if (t < G_ * R_) {
        const int g = t >> 4, r = t & 15;
        float acc = b1[g * R_ + r];
        const float* __restrict__ w1p = W1 + (size_t)g * (2 * CG_) * R_ + r;
        const float* gf = comb + g * (2 * CG_);
#pragma unroll 8
        for (int i = 0; i < 2 * CG_; i++)
            acc = fmaf(gf[i], w1p[(size_t)i * R_], acc);
        hsm[t] = fmaxf(acc, 0.0f);
    }
    __syncthreads();

    // Output layer: score[c], c = t; group g = t/128, o = t%128.
    const int g = t >> 7, o = t & 127;
    float sc = b2[g * CG_ + o];
    const float* __restrict__ w2p = W2 + (size_t)g * R_ * CG_ + o;
#pragma unroll
    for (int r = 0; r < R_; r++)
        sc = fmaf(hsm[g * R_ + r], w2p[(size_t)r * CG_], sc);
    scores[t] = sc;
    __syncthreads();

    // Exact top-k rank: matches jax.lax.top_k (descending value, lowest index
    // wins ties). Broadcast smem reads: all threads read scores[j] together.
    int rank = 0;
    for (int j = 0; j < C_; j++) {
        const float sj = scores[j];
        rank += (sj > sc) || (sj == sc && j < t);
    }
    const float hard = (rank < TOPK_) ? 1.0f : 0.0f;

    // Gumbel-sigmoid soft score (precise logf/expf: 8192 threads total, cheap)
    const float u   = noise_u[b * C_ + t];
    const float gum = -logf(-logf(u + EPS_) + EPS_);
    const float z   = (sc + gum) * TAU_INV;
    const float soft = 1.0f / (1.0f + expf(-z));

    const float mask = hard * soft;
    g_blend[b * C_ + t] = mask + (1.0f - mask) * ALPHA_;
}

// ---------------------------------------------------------------------------
// Kernel 3: out = x * blend[b,c]. One block per (b,c), float4 vectorized.
// REVERSED bc mapping: pool read x in ascending-bc wave order, so the last
// ~126 MB of x is L2-resident when blend starts. Reading in descending bc
// order converts that window into L2 hits (~6% less DRAM traffic).
// __ldcs still hits L2 when present; __stcs keeps the store stream from
// evicting the reused x lines (both evict-first).
// ---------------------------------------------------------------------------
__global__ __launch_bounds__(T1) void blend_kernel(
    const float* __restrict__ x, float* __restrict__ out, int BC)
{
    const int bc = BC - 1 - blockIdx.x;     // hottest-in-L2 lines first
    const float bl = g_blend[bc];
    const size_t base = (size_t)bc * HW_;
    const float4* __restrict__ xp = reinterpret_cast<const float4*>(x + base);
    float4* __restrict__ op       = reinterpret_cast<float4*>(out + base);
    const int t = threadIdx.x;
#pragma unroll
    for (int k = 0; k < PER_T; k++) {
        const int i = t + k * T1;
        float4 v = __ldcs(&xp[i]);      // evict-first load (hits L2 if present)
        v.x *= bl; v.y *= bl; v.z *= bl; v.w *= bl;
        __stcs(&op[i], v);              // streaming store
    }
}

// ---------------------------------------------------------------------------
extern "C" void kernel_launch(void* const* d_in, const int* in_sizes, int n_in,
                              void* d_out, int out_size)
{
    const float* x  = (const float*)d_in[0];
    const float* W1 = (const float*)d_in[1];
    const float* b1 = (const float*)d_in[2];
    const float* W2 = (const float*)d_in[3];
    const float* b2 = (const float*)d_in[4];
    const float* nu = (const float*)d_in[5];
    float* out = (float*)d_out;

    const int B  = in_sizes[5] / C_;   // noise_u is [B, C]
    const int BC = B * C_;

    pool_kernel <<<BC, T1>>>(x);
    score_kernel<<<B,  C_>>>(W1, b1, W2, b2, nu);
    blend_kernel<<<BC, T1>>>(x, out, BC);
}